// round 12
// baseline (speedup 1.0000x reference)
#include <cuda_runtime.h>
#include <cuda_bf16.h>
#include <cstdint>

#define B_ROWS 16384
#define L_COLS 1024
#define ROWS_PER_BLK 16
#define NBLKS (B_ROWS / ROWS_PER_BLK)   // 1024
#define FIX_SCALE 4294967296.0          // 2^32

// Fence-free cross-block accumulator (no device allocation allowed).
__device__ unsigned long long g_acc = 0ULL;   // fixed-point sum of row losses
__device__ unsigned int g_count = 0u;         // completed-block counter

// 1024 blocks x 512 threads (16 warps). Warp w handles row blockIdx.x*16 + w.
// Each lane: 8 iterations of (float4 c, int4 y) -> 1024 elems/row.
// launch_bounds(512, 4) caps regs -> 4 blocks/SM -> 100% occupancy.
// Finish: per-block loss sum -> 2^32 fixed point -> integer atomicAdd
// (exactly commutative => deterministic). Last block writes the mean.
// NO __threadfence anywhere (gpu-scope fence = CCTL.IVALL L1 flush, the
// thing that killed the R3 fused version).
__global__ void __launch_bounds__(512, 4)
bpmll_fused_kernel(const float* __restrict__ c, const int* __restrict__ y,
                   float* __restrict__ out) {
    const int t = threadIdx.x;
    const int warp = t >> 5;
    const int lane = t & 31;
    const int row = blockIdx.x * ROWS_PER_BLK + warp;

    const float4* __restrict__ c4 =
        reinterpret_cast<const float4*>(c + (size_t)row * L_COLS);
    const int4* __restrict__ y4 =
        reinterpret_cast<const int4*>(y + (size_t)row * L_COLS);

    float pos = 0.0f, neg = 0.0f;
    int yc = 0;

    #pragma unroll
    for (int i = 0; i < 8; i++) {
        const float4 cv = c4[i * 32 + lane];
        const int4 yv = y4[i * 32 + lane];

        {
            const float e = __expf(yv.x ? -cv.x : cv.x);
            if (yv.x) { pos += e; yc++; } else { neg += e; }
        }
        {
            const float e = __expf(yv.y ? -cv.y : cv.y);
            if (yv.y) { pos += e; yc++; } else { neg += e; }
        }
        {
            const float e = __expf(yv.z ? -cv.z : cv.z);
            if (yv.z) { pos += e; yc++; } else { neg += e; }
        }
        {
            const float e = __expf(yv.w ? -cv.w : cv.w);
            if (yv.w) { pos += e; yc++; } else { neg += e; }
        }
    }

    // Warp tree reduction (deterministic).
    #pragma unroll
    for (int off = 16; off > 0; off >>= 1) {
        pos += __shfl_down_sync(0xFFFFFFFFu, pos, off);
        neg += __shfl_down_sync(0xFFFFFFFFu, neg, off);
        yc  += __shfl_down_sync(0xFFFFFFFFu, yc, off);
    }

    __shared__ float s_loss[ROWS_PER_BLK];
    if (lane == 0) {
        const float yn = (float)yc;
        const float ybn = (float)(L_COLS - yc);
        s_loss[warp] = (pos * neg) / (yn * ybn);
    }
    __syncthreads();

    if (t == 0) {
        // Fixed order -> deterministic block sum.
        float sum = 0.0f;
        #pragma unroll
        for (int w = 0; w < ROWS_PER_BLK; w++) sum += s_loss[w];

        // Convert to 2^32 fixed point (double for the scale multiply).
        const unsigned long long fixed =
            (unsigned long long)((double)sum * FIX_SCALE + 0.5);

        // Accumulate. atomicAdd returns old value => the L2 RMW has
        // completed before we proceed.
        const unsigned long long old = atomicAdd(&g_acc, fixed);

        // Chain the counter on the returned value so the acc-add is
        // ordered before the count-add without any fence.
        const unsigned int dep = (unsigned int)(old & 1ULL);
        const unsigned int prev = atomicAdd(&g_count, 1u + dep - dep);

        if (prev == (unsigned int)(NBLKS - 1)) {
            // All blocks' acc-adds precede their count-adds; seeing the
            // final count => g_acc holds the full total.
            const unsigned long long total = atomicExch(&g_acc, 0ULL);
            out[0] = (float)((double)total * (1.0 / FIX_SCALE)
                             * (1.0 / (double)B_ROWS));
            atomicExch(&g_count, 0u);  // reset for next graph replay
        }
    }
}

extern "C" void kernel_launch(void* const* d_in, const int* in_sizes, int n_in,
                              void* d_out, int out_size) {
    const float* c = (const float*)d_in[0];
    const int* y = (const int*)d_in[1];
    float* out = (float*)d_out;

    bpmll_fused_kernel<<<NBLKS, 512>>>(c, y, out);
}